// round 2
// baseline (speedup 1.0000x reference)
#include <cuda_runtime.h>
#include <math.h>

#define BB 32
#define SS 4096
#define VD 512
#define HD 512
#define QD 512
#define CTX_SIZE (BB*VD)
#define TM 32
#define PAD 36
#define NSPLIT 8

// Scratch (no allocations allowed)
__device__ float g_qp[BB*HD];
__device__ float g_scores[BB*SS];
__device__ float g_cpart[NSPLIT*BB*VD];

// ---------------- Kernel 1: qp[b,h] = query[b]·Wq[:,h] + bq[h] ----------------
__global__ void qp_kernel(const float* __restrict__ query,
                          const float* __restrict__ Wq,
                          const float* __restrict__ bq) {
    int b = blockIdx.x;
    int h = threadIdx.x;              // 512 threads
    __shared__ float qs[QD];
    qs[h] = query[b*QD + h];
    __syncthreads();
    float acc = 0.f;
    #pragma unroll 8
    for (int v = 0; v < QD; v++) acc += qs[v] * Wq[v*HD + h];
    g_qp[b*HD + h] = acc + bq[h];
}

// ---------------- Kernel 2: scores[b,s] = Wo·tanh(qp[b] + value[b,s]·Wk) + bo ----
// Block: 32 rows of (b,s). 256 threads: c = tid&63 (h within 64-wide tile),
// rg = tid>>6 selects 8 rows. value rows cached transposed in SMEM (pad 36).
__global__ void score_kernel(const float* __restrict__ value,
                             const float* __restrict__ Wk,
                             const float* __restrict__ Wo,
                             const float* __restrict__ bo) {
    extern __shared__ float sm[];
    float* sVt  = sm;                 // VD*PAD = 18432 floats
    float* qp_s = sm + VD*PAD;        // HD
    float* wo_s = qp_s + HD;          // HD
    float* red  = wo_s + HD;          // TM

    const int b   = blockIdx.y;
    const int s0  = blockIdx.x * TM;
    const int tid = threadIdx.x;

    const float* vbase = value + ((size_t)(b*SS + s0)) * VD;
    // Load 32x512 value rows, transposed: sVt[v*PAD + r]
    for (int idx = tid; idx < TM*VD; idx += 256) {
        int r = idx >> 9;             // idx / 512
        int v = idx & 511;
        sVt[v*PAD + r] = vbase[(size_t)r*VD + v];
    }
    for (int i = tid; i < HD; i += 256) {
        qp_s[i] = g_qp[b*HD + i];
        wo_s[i] = Wo[i];
    }
    if (tid < TM) red[tid] = 0.f;
    __syncthreads();

    const int c  = tid & 63;
    const int rg = tid >> 6;
    const int rowbase = rg * 8;

    float scoreAcc[8];
    #pragma unroll
    for (int i = 0; i < 8; i++) scoreAcc[i] = 0.f;

    for (int h0 = 0; h0 < HD; h0 += 64) {
        const int h = h0 + c;
        float acc[8];
        #pragma unroll
        for (int i = 0; i < 8; i++) acc[i] = 0.f;

        const float* wp = Wk + h;     // Wk[v*HD + h]
        #pragma unroll 4
        for (int v = 0; v < VD; v++) {
            float w = __ldg(wp + v*HD);
            float4 a0 = *(const float4*)&sVt[v*PAD + rowbase];
            float4 a1 = *(const float4*)&sVt[v*PAD + rowbase + 4];
            acc[0] += a0.x * w;  acc[1] += a0.y * w;
            acc[2] += a0.z * w;  acc[3] += a0.w * w;
            acc[4] += a1.x * w;  acc[5] += a1.y * w;
            acc[6] += a1.z * w;  acc[7] += a1.w * w;
        }
        const float qh  = qp_s[h];
        const float woh = wo_s[h];
        #pragma unroll
        for (int i = 0; i < 8; i++)
            scoreAcc[i] += woh * tanhf(acc[i] + qh);
    }

    // Reduce over the 64 h-lanes: shuffle within warp, then smem across warps.
    #pragma unroll
    for (int i = 0; i < 8; i++) {
        #pragma unroll
        for (int off = 16; off > 0; off >>= 1)
            scoreAcc[i] += __shfl_down_sync(0xffffffffu, scoreAcc[i], off);
    }
    if ((tid & 31) == 0) {
        #pragma unroll
        for (int i = 0; i < 8; i++)
            atomicAdd(&red[rowbase + i], scoreAcc[i]);
    }
    __syncthreads();
    if (tid < TM)
        g_scores[b*SS + s0 + tid] = red[tid] + bo[0];
}

// ---------------- Kernel 3: masked softmax over S per batch row ----------------
// NOTE: mask arrives as int32 (bool is promoted by the harness).
__global__ void softmax_kernel(const int* __restrict__ mask,
                               float* __restrict__ att_out) {
    const int b = blockIdx.x;
    const int tid = threadIdx.x;      // 256
    __shared__ float sred[256];

    // pass 1: apply mask, find max
    float m = -3.0e38f;
    for (int s = tid; s < SS; s += 256) {
        float sc = (mask[b*SS + s] != 0) ? g_scores[b*SS + s] : -1e9f;
        g_scores[b*SS + s] = sc;
        m = fmaxf(m, sc);
    }
    sred[tid] = m; __syncthreads();
    for (int off = 128; off > 0; off >>= 1) {
        if (tid < off) sred[tid] = fmaxf(sred[tid], sred[tid + off]);
        __syncthreads();
    }
    m = sred[0];
    __syncthreads();

    // pass 2: exp + sum
    float sum = 0.f;
    for (int s = tid; s < SS; s += 256) {
        float e = expf(g_scores[b*SS + s] - m);
        att_out[b*SS + s] = e;
        sum += e;
    }
    sred[tid] = sum; __syncthreads();
    for (int off = 128; off > 0; off >>= 1) {
        if (tid < off) sred[tid] += sred[tid + off];
        __syncthreads();
    }
    const float inv = 1.f / sred[0];
    __syncthreads();

    // pass 3: normalize
    for (int s = tid; s < SS; s += 256)
        att_out[b*SS + s] *= inv;
}

// ---------------- Kernel 4: ctx partials (deterministic split over S) ----------
__global__ void ctx_part_kernel(const float* __restrict__ value,
                                const float* __restrict__ att) {
    const int v  = blockIdx.x * 256 + threadIdx.x;
    const int sc = blockIdx.y;        // 0..7
    const int b  = blockIdx.z;
    const int s0 = sc * (SS / NSPLIT);

    const float* vb = value + ((size_t)(b*SS + s0)) * VD + v;
    const float* ab = att + b*SS + s0;
    float acc = 0.f;
    #pragma unroll 4
    for (int s = 0; s < SS / NSPLIT; s++)
        acc = fmaf(ab[s], vb[(size_t)s * VD], acc);
    g_cpart[sc*(BB*VD) + b*VD + v] = acc;
}

// ---------------- Kernel 5: reduce partials -> ctx -----------------------------
__global__ void ctx_reduce_kernel(float* __restrict__ ctx) {
    const int idx = blockIdx.x * 256 + threadIdx.x;  // 0..BB*VD-1
    float acc = 0.f;
    #pragma unroll
    for (int p = 0; p < NSPLIT; p++)
        acc += g_cpart[p*(BB*VD) + idx];
    ctx[idx] = acc;
}

extern "C" void kernel_launch(void* const* d_in, const int* in_sizes, int n_in,
                              void* d_out, int out_size) {
    const float* query = (const float*)d_in[0];
    const float* value = (const float*)d_in[1];
    const int*   mask  = (const int*)d_in[2];   // bool promoted to int32
    const float* Wk    = (const float*)d_in[3];
    const float* Wq    = (const float*)d_in[4];
    const float* bq    = (const float*)d_in[5];
    const float* Wo    = (const float*)d_in[6];
    const float* bo    = (const float*)d_in[7];

    float* out = (float*)d_out;
    float* ctx = out;                 // [B, VD]
    float* att = out + CTX_SIZE;      // [B, S]

    qp_kernel<<<BB, 512>>>(query, Wq, bq);

    const size_t smem = (size_t)(VD*PAD + HD + HD + TM) * sizeof(float);
    cudaFuncSetAttribute(score_kernel,
                         cudaFuncAttributeMaxDynamicSharedMemorySize, (int)smem);
    score_kernel<<<dim3(SS/TM, BB), 256, smem>>>(value, Wk, Wo, bo);

    softmax_kernel<<<BB, 256>>>(mask, att);

    ctx_part_kernel<<<dim3(VD/256, NSPLIT, BB), 256>>>(value, att);
    ctx_reduce_kernel<<<(BB*VD)/256, 256>>>(ctx);
}

// round 5
// speedup vs baseline: 10.9270x; 10.9270x over previous
#include <cuda_runtime.h>
#include <cuda_fp16.h>
#include <math.h>
#include <stdint.h>

#define BB 32
#define SS 4096
#define VD 512
#define HD 512
#define QD 512
#define CTX_SIZE (BB*VD)
#define CSPLIT 16

// -------- scratch (no allocation allowed) --------
__device__ float  g_qp[BB*HD];
__device__ float  g_scores[BB*SS];
__device__ float  g_cpart[CSPLIT*BB*VD];
__device__ __half g_WkT[HD*VD];   // [h][v] fp16 (B operand, K-major "col" layout)

// ---------------- helpers ----------------
__device__ __forceinline__ uint32_t smem_u32(const void* p) {
    uint32_t a;
    asm("{ .reg .u64 t; cvta.to.shared.u64 t, %1; cvt.u32.u64 %0, t; }"
        : "=r"(a) : "l"(p));
    return a;
}
__device__ __forceinline__ void ldsm4(uint32_t* r, uint32_t addr) {
    asm volatile("ldmatrix.sync.aligned.m8n8.x4.shared.b16 {%0,%1,%2,%3}, [%4];"
        : "=r"(r[0]), "=r"(r[1]), "=r"(r[2]), "=r"(r[3]) : "r"(addr));
}
__device__ __forceinline__ void mma16816(float* d, const uint32_t* a, const uint32_t* b) {
    asm volatile("mma.sync.aligned.m16n8k16.row.col.f32.f16.f16.f32 "
        "{%0,%1,%2,%3}, {%4,%5,%6,%7}, {%8,%9}, {%0,%1,%2,%3};"
        : "+f"(d[0]), "+f"(d[1]), "+f"(d[2]), "+f"(d[3])
        : "r"(a[0]), "r"(a[1]), "r"(a[2]), "r"(a[3]), "r"(b[0]), "r"(b[1]));
}
__device__ __forceinline__ float tanha(float x) {
    float y;
    asm("tanh.approx.f32 %0, %1;" : "=f"(y) : "f"(x));
    return y;
}

// ---------------- Kernel 1: qp[b,h] = query[b]·Wq[:,h] + bq[h] ----------------
__global__ void qp_kernel(const float* __restrict__ query,
                          const float* __restrict__ Wq,
                          const float* __restrict__ bq) {
    int b = blockIdx.x;
    int h = threadIdx.x;              // 512
    __shared__ float qs[QD];
    qs[h] = query[b*QD + h];
    __syncthreads();
    float acc = 0.f;
    #pragma unroll 8
    for (int v = 0; v < QD; v++) acc += qs[v] * Wq[v*HD + h];
    g_qp[b*HD + h] = acc + bq[h];
}

// ---------------- Kernel 1b: WkT[h][v] = fp16(Wk[v][h]) ----------------
__global__ void wkt_kernel(const float* __restrict__ Wk) {
    int h = blockIdx.x;
    int v = threadIdx.x;              // 512
    g_WkT[h*VD + v] = __float2half_rn(Wk[v*HD + h]);
}

// ---------------- Kernel 2: mma.sync score GEMM + fused tanh epilogue ---------
// CTA: 128 rows (flat b*S+s). A[128x512] fp16 in smem (pad 520), loaded once.
// h-tiles of 64 (8 tiles): stage B=WkT[64x512] (pad 520), K-loop 32x k16,
// epilogue score += Wo[h]*tanh(acc+qp[h]).
#define APAD 520
#define OFF_A   0
#define OFF_B   133120
#define OFF_QP  199680
#define OFF_WO  201728
#define OFF_RED 203776
#define SMEM_TOTAL (204288 + 256)

__global__ __launch_bounds__(256, 1)
void score_mma_kernel(const float* __restrict__ value,
                      const float* __restrict__ Wo,
                      const float* __restrict__ bo) {
    extern __shared__ char sm[];
    const uint32_t sbase = smem_u32(sm);
    const int tid = threadIdx.x;
    const int L   = tid & 31;
    const int wid = tid >> 5;
    const int mw  = wid & 3;          // M-warp: rows mw*32..+31
    const int nw  = wid >> 2;         // N-warp: h-cols nw*32..+31 within tile
    const int b   = blockIdx.x >> 5;
    const size_t row0 = (size_t)blockIdx.x * 128;

    __half* As  = (__half*)(sm + OFF_A);
    __half* Bs  = (__half*)(sm + OFF_B);
    float* qp_s = (float*)(sm + OFF_QP);
    float* wo_s = (float*)(sm + OFF_WO);
    float* red  = (float*)(sm + OFF_RED);

    // ---- stage A: value[row0..+127][0..511] f32 -> fp16, pad 520 ----
    // 128 rows x 128 float4/row = 16384 -> 64 iterations of 256 threads
    {
        const float* vsrc = value + row0 * VD;
        #pragma unroll
        for (int it = 0; it < 64; it++) {
            int i  = tid + it*256;            // 0..16383
            int r  = i >> 7;                  // 128 float4 per row
            int f4 = i & 127;
            float4 f = *(const float4*)(vsrc + (size_t)r*VD + f4*4);
            __half2 h0 = __floats2half2_rn(f.x, f.y);
            __half2 h1 = __floats2half2_rn(f.z, f.w);
            *(uint2*)(As + r*APAD + f4*4) =
                make_uint2(*(uint32_t*)&h0, *(uint32_t*)&h1);
        }
    }
    for (int i = tid; i < HD; i += 256) {
        qp_s[i] = g_qp[b*HD + i];
        wo_s[i] = Wo[i];
    }
    if (tid < 128) red[tid] = 0.f;

    // ldmatrix lane addresses (bytes)
    const uint32_t aAddr = sbase + OFF_A +
        (uint32_t)(((mw*32 + (L & 15))*APAD + (L >> 4)*8) * 2);
    const uint32_t bAddr = sbase + OFF_B +
        (uint32_t)(((nw*32 + (L & 7) + ((L >> 4) << 3))*APAD + ((L >> 3) & 1)*8) * 2);

    float sp[4] = {0.f, 0.f, 0.f, 0.f};      // per-lane score partials

    for (int t = 0; t < 8; t++) {
        __syncthreads();                      // prev tile's compute done
        // ---- stage B tile: WkT[t*64 .. +63][0..511] ----
        #pragma unroll
        for (int it = 0; it < 16; it++) {
            int i = tid + it*256;             // 0..4095
            int n = i >> 6;                   // 64 uint4 per row
            int g = i & 63;
            uint4 u = *(const uint4*)(g_WkT + ((size_t)(t*64 + n))*VD + g*8);
            *(uint4*)(Bs + n*APAD + g*8) = u;
        }
        __syncthreads();

        float acc[2][4][4];
        #pragma unroll
        for (int mi = 0; mi < 2; mi++)
            #pragma unroll
            for (int ni = 0; ni < 4; ni++)
                #pragma unroll
                for (int j = 0; j < 4; j++) acc[mi][ni][j] = 0.f;

        #pragma unroll 8
        for (int ks = 0; ks < 32; ks++) {
            const uint32_t kb = ks * 32;      // k0*2 bytes (k0 = ks*16)
            uint32_t a0[4], a1[4], b0[4], b1[4];
            ldsm4(a0, aAddr + kb);
            ldsm4(a1, aAddr + 16*APAD*2 + kb);
            ldsm4(b0, bAddr + kb);
            ldsm4(b1, bAddr + 16*APAD*2 + kb);
            mma16816(acc[0][0], a0, b0 + 0);
            mma16816(acc[0][1], a0, b0 + 2);
            mma16816(acc[0][2], a0, b1 + 0);
            mma16816(acc[0][3], a0, b1 + 2);
            mma16816(acc[1][0], a1, b0 + 0);
            mma16816(acc[1][1], a1, b0 + 2);
            mma16816(acc[1][2], a1, b1 + 0);
            mma16816(acc[1][3], a1, b1 + 2);
        }

        // ---- epilogue: sp += Wo[h] * tanh(acc + qp[h]) ----
        #pragma unroll
        for (int ni = 0; ni < 4; ni++) {
            const int hb = t*64 + nw*32 + ni*8 + 2*(L & 3);
            const float qp0 = qp_s[hb],   qp1 = qp_s[hb + 1];
            const float wo0 = wo_s[hb],   wo1 = wo_s[hb + 1];
            #pragma unroll
            for (int mi = 0; mi < 2; mi++) {
                float t0 = tanha(acc[mi][ni][0] + qp0);
                float t1 = tanha(acc[mi][ni][1] + qp1);
                float t2 = tanha(acc[mi][ni][2] + qp0);
                float t3 = tanha(acc[mi][ni][3] + qp1);
                sp[mi*2 + 0] += wo0*t0 + wo1*t1;   // row L/4 (+ mi*16)
                sp[mi*2 + 1] += wo0*t2 + wo1*t3;   // row L/4 + 8 (+ mi*16)
            }
        }
    }

    // reduce 4 lanes sharing a row (L^1, L^2), then combine 2 N-warps via smem
    #pragma unroll
    for (int i = 0; i < 4; i++) {
        sp[i] += __shfl_xor_sync(0xffffffffu, sp[i], 1);
        sp[i] += __shfl_xor_sync(0xffffffffu, sp[i], 2);
    }
    if ((L & 3) == 0) {
        const int mr = mw*32 + (L >> 2);
        atomicAdd(&red[mr +  0], sp[0]);
        atomicAdd(&red[mr +  8], sp[1]);
        atomicAdd(&red[mr + 16], sp[2]);
        atomicAdd(&red[mr + 24], sp[3]);
    }
    __syncthreads();
    if (tid < 128)
        g_scores[row0 + tid] = red[tid] + bo[0];
}

// ---------------- Kernel 3: masked softmax (mask is int32) ----------------
__global__ void softmax_kernel(const int* __restrict__ mask,
                               float* __restrict__ att_out) {
    const int b = blockIdx.x;
    const int tid = threadIdx.x;      // 256
    __shared__ float sred[256];

    float m = -3.0e38f;
    for (int s = tid; s < SS; s += 256) {
        float sc = (mask[b*SS + s] != 0) ? g_scores[b*SS + s] : -1e9f;
        g_scores[b*SS + s] = sc;
        m = fmaxf(m, sc);
    }
    sred[tid] = m; __syncthreads();
    for (int off = 128; off > 0; off >>= 1) {
        if (tid < off) sred[tid] = fmaxf(sred[tid], sred[tid + off]);
        __syncthreads();
    }
    m = sred[0];
    __syncthreads();

    float sum = 0.f;
    for (int s = tid; s < SS; s += 256) {
        float e = expf(g_scores[b*SS + s] - m);
        att_out[b*SS + s] = e;
        sum += e;
    }
    sred[tid] = sum; __syncthreads();
    for (int off = 128; off > 0; off >>= 1) {
        if (tid < off) sred[tid] += sred[tid + off];
        __syncthreads();
    }
    const float inv = 1.f / sred[0];
    __syncthreads();

    for (int s = tid; s < SS; s += 256)
        att_out[b*SS + s] *= inv;
}

// ---------------- Kernel 4: ctx partials (float4 per thread, staged att) -------
__global__ __launch_bounds__(128)
void ctx_part_kernel(const float* __restrict__ value,
                     const float* __restrict__ att) {
    __shared__ float atts[SS / CSPLIT];          // 256
    const int b = blockIdx.y, sc = blockIdx.x, t = threadIdx.x;
    const int s0 = sc * (SS / CSPLIT);

    for (int i = t; i < SS / CSPLIT; i += 128)
        atts[i] = att[b*SS + s0 + i];
    __syncthreads();

    const float* vb = value + ((size_t)(b*SS + s0))*VD + t*4;
    float ax = 0.f, ay = 0.f, az = 0.f, aw = 0.f;
    #pragma unroll 4
    for (int s = 0; s < SS / CSPLIT; s++) {
        float a = atts[s];
        float4 v4 = *(const float4*)(vb + (size_t)s*VD);
        ax = fmaf(a, v4.x, ax); ay = fmaf(a, v4.y, ay);
        az = fmaf(a, v4.z, az); aw = fmaf(a, v4.w, aw);
    }
    float4 r = make_float4(ax, ay, az, aw);
    *(float4*)&g_cpart[((size_t)sc*BB + b)*VD + t*4] = r;
}

// ---------------- Kernel 5: reduce partials -> ctx -----------------------------
__global__ void ctx_reduce_kernel(float* __restrict__ ctx) {
    const int idx = blockIdx.x * 256 + threadIdx.x;  // 0..BB*VD-1
    float acc = 0.f;
    #pragma unroll
    for (int p = 0; p < CSPLIT; p++)
        acc += g_cpart[(size_t)p*(BB*VD) + idx];
    ctx[idx] = acc;
}

extern "C" void kernel_launch(void* const* d_in, const int* in_sizes, int n_in,
                              void* d_out, int out_size) {
    const float* query = (const float*)d_in[0];
    const float* value = (const float*)d_in[1];
    const int*   mask  = (const int*)d_in[2];   // bool promoted to int32
    const float* Wk    = (const float*)d_in[3];
    const float* Wq    = (const float*)d_in[4];
    const float* bq    = (const float*)d_in[5];
    const float* Wo    = (const float*)d_in[6];
    const float* bo    = (const float*)d_in[7];

    float* out = (float*)d_out;
    float* ctx = out;                 // [B, VD]
    float* att = out + CTX_SIZE;      // [B, S]

    qp_kernel<<<BB, 512>>>(query, Wq, bq);
    wkt_kernel<<<HD, VD>>>(Wk);

    cudaFuncSetAttribute(score_mma_kernel,
                         cudaFuncAttributeMaxDynamicSharedMemorySize, SMEM_TOTAL);
    score_mma_kernel<<<(BB*SS)/128, 256, SMEM_TOTAL>>>(value, Wo, bo);

    softmax_kernel<<<BB, 256>>>(mask, att);

    ctx_part_kernel<<<dim3(CSPLIT, BB), 128>>>(value, att);
    ctx_reduce_kernel<<<(BB*VD)/256, 256>>>(ctx);
}